// round 4
// baseline (speedup 1.0000x reference)
#include <cuda_runtime.h>

// Problem constants (fixed shapes from reference)
#define BB 16
#define HH 512
#define WW 512
#define H2 1024
#define W2 1024
#define WV8 (W2 / 8)   // 8-col tiles per output row = 128

// Fused: bilinear 2x upsample of mask (2ch) -> x_mask,y_mask;
// fused_c = xm*xl_c + ym*yl_c; out_o = relu(sum_i w[o,i]*fused_i + b_o).
// R4: one thread = 2 output rows (even/odd pair) x 8 columns, all channels.
// 24 float4 loads per thread for deep MLP; mask taps shared across the tile.
__global__ void __launch_bounds__(256) fused_upsample_blend_conv_kernel(
    const float* __restrict__ mask,   // (B,2,H,W)
    const float* __restrict__ xl,     // (B,3,H2,W2)
    const float* __restrict__ yl,     // (B,3,H2,W2)
    const float* __restrict__ cw,     // (3,3) row-major 'oi'
    const float* __restrict__ cb,     // (3,)
    float* __restrict__ out)          // (B,3,H2,W2) ++ (B,1,H2,W2) ++ (B,1,H2,W2)
{
    int idx = blockIdx.x * blockDim.x + threadIdx.x;
    int ox8 = idx & (WV8 - 1);       // 8-col tile index along width
    int t   = idx >> 7;              // WV8 = 128
    int k   = t & (HH - 1);          // input row / output row-pair index
    int b   = t >> 9;                // HH = 512
    if (b >= BB) return;

    // Output rows: oy0 = 2k (even: rows k-1,k w 0.25/0.75),
    //              oy1 = 2k+1 (odd: rows k,k+1 w 0.75/0.25)
    int km1 = k - 1; if (km1 < 0) km1 = 0;
    int kp1 = k + 1; if (kp1 > HH - 1) kp1 = HH - 1;

    // ---- horizontal: 8 outputs need input cols n-1 .. n+4 (6 cols) ----
    int n = ox8 * 4;                         // 0..508
    int col[6];
    col[0] = n - 1; if (col[0] < 0) col[0] = 0;
    col[1] = n; col[2] = n + 1; col[3] = n + 2; col[4] = n + 3;
    col[5] = n + 4; if (col[5] > WW - 1) col[5] = WW - 1;

    const size_t mplane = (size_t)HH * WW;
    const float* mx = mask + ((size_t)b * 2 + 0) * mplane;
    const float* my = mask + ((size_t)b * 2 + 1) * mplane;
    const float* mx_m = mx + (size_t)km1 * WW;
    const float* mx_0 = mx + (size_t)k   * WW;
    const float* mx_p = mx + (size_t)kp1 * WW;
    const float* my_m = my + (size_t)km1 * WW;
    const float* my_0 = my + (size_t)k   * WW;
    const float* my_p = my + (size_t)kp1 * WW;

    // raw mask samples: 3 rows x 6 cols x 2 channels
    float xA[6], xB[6], xC[6], yA[6], yB[6], yC[6];
    #pragma unroll
    for (int i = 0; i < 6; i++) {
        xA[i] = __ldg(mx_m + col[i]);
        xB[i] = __ldg(mx_0 + col[i]);
        xC[i] = __ldg(mx_p + col[i]);
        yA[i] = __ldg(my_m + col[i]);
        yB[i] = __ldg(my_0 + col[i]);
        yC[i] = __ldg(my_p + col[i]);
    }

    // vertical interpolation per input column, for even (e) and odd (o) rows
    float vxe[6], vxo[6], vye[6], vyo[6];
    #pragma unroll
    for (int i = 0; i < 6; i++) {
        vxe[i] = 0.25f * xA[i] + 0.75f * xB[i];
        vxo[i] = 0.75f * xB[i] + 0.25f * xC[i];
        vye[i] = 0.25f * yA[i] + 0.75f * yB[i];
        vyo[i] = 0.75f * yB[i] + 0.25f * yC[i];
    }

    // horizontal combine -> per-row 8-wide masks
    // even out j: 0.25*v[j/2] + 0.75*v[j/2+1]; odd: 0.75*v[(j+1)/2] + 0.25*v[(j+1)/2+1]
    float xme[8], xmo[8], yme[8], ymo[8];
    #pragma unroll
    for (int j = 0; j < 8; j++) {
        int lo = (j + (j & 1)) >> 1;         // even: j/2, odd: (j+1)/2
        float wa = (j & 1) ? 0.75f : 0.25f;
        float wb = (j & 1) ? 0.25f : 0.75f;
        xme[j] = wa * vxe[lo] + wb * vxe[lo + 1];
        xmo[j] = wa * vxo[lo] + wb * vxo[lo + 1];
        yme[j] = wa * vye[lo] + wb * vye[lo + 1];
        ymo[j] = wa * vyo[lo] + wb * vyo[lo + 1];
    }

    // conv weights / bias
    float W[3][3], B3[3];
    #pragma unroll
    for (int o = 0; o < 3; o++) {
        #pragma unroll
        for (int i = 0; i < 3; i++) W[o][i] = __ldg(cw + o * 3 + i);
        B3[o] = __ldg(cb + o);
    }

    const size_t plane = (size_t)H2 * W2;
    const int oy0 = 2 * k;
    const size_t base0 = (size_t)b * 3 * plane + (size_t)oy0 * W2 + (size_t)ox8 * 8;

    float* out_main = out;                                   // (B,3,H2,W2)
    float* out_xm   = out + (size_t)BB * 3 * plane;          // (B,1,H2,W2)
    float* out_ym   = out_xm + (size_t)BB * plane;           // (B,1,H2,W2)

    #pragma unroll
    for (int r = 0; r < 2; r++) {
        const float* xm = r ? xmo : xme;
        const float* ym = r ? ymo : yme;
        const size_t base = base0 + (size_t)r * W2;

        // accumulators = bias
        float acc0[8], acc1[8], acc2[8];
        #pragma unroll
        for (int j = 0; j < 8; j++) { acc0[j] = B3[0]; acc1[j] = B3[1]; acc2[j] = B3[2]; }

        // per input channel: load 8 xl + 8 yl, blend, accumulate into 3 outputs
        #pragma unroll
        for (int c = 0; c < 3; c++) {
            const size_t cb8 = base + (size_t)c * plane;
            float4 xa = *(const float4*)(xl + cb8);
            float4 xb = *(const float4*)(xl + cb8 + 4);
            float4 ya = *(const float4*)(yl + cb8);
            float4 yb = *(const float4*)(yl + cb8 + 4);
            float xv[8] = { xa.x, xa.y, xa.z, xa.w, xb.x, xb.y, xb.z, xb.w };
            float yv[8] = { ya.x, ya.y, ya.z, ya.w, yb.x, yb.y, yb.z, yb.w };
            #pragma unroll
            for (int j = 0; j < 8; j++) {
                float f = xm[j] * xv[j] + ym[j] * yv[j];
                acc0[j] += W[0][c] * f;
                acc1[j] += W[1][c] * f;
                acc2[j] += W[2][c] * f;
            }
        }

        // relu + store (3 channels x 2 float4 + 2 masks x 2 float4)
        #pragma unroll
        for (int j = 0; j < 8; j++) {
            acc0[j] = acc0[j] > 0.0f ? acc0[j] : 0.0f;
            acc1[j] = acc1[j] > 0.0f ? acc1[j] : 0.0f;
            acc2[j] = acc2[j] > 0.0f ? acc2[j] : 0.0f;
        }
        *(float4*)(out_main + base)                 = make_float4(acc0[0], acc0[1], acc0[2], acc0[3]);
        *(float4*)(out_main + base + 4)             = make_float4(acc0[4], acc0[5], acc0[6], acc0[7]);
        *(float4*)(out_main + base + plane)         = make_float4(acc1[0], acc1[1], acc1[2], acc1[3]);
        *(float4*)(out_main + base + plane + 4)     = make_float4(acc1[4], acc1[5], acc1[6], acc1[7]);
        *(float4*)(out_main + base + 2 * plane)     = make_float4(acc2[0], acc2[1], acc2[2], acc2[3]);
        *(float4*)(out_main + base + 2 * plane + 4) = make_float4(acc2[4], acc2[5], acc2[6], acc2[7]);

        size_t mbase = (size_t)b * plane + (size_t)(oy0 + r) * W2 + (size_t)ox8 * 8;
        *(float4*)(out_xm + mbase)     = make_float4(xm[0], xm[1], xm[2], xm[3]);
        *(float4*)(out_xm + mbase + 4) = make_float4(xm[4], xm[5], xm[6], xm[7]);
        *(float4*)(out_ym + mbase)     = make_float4(ym[0], ym[1], ym[2], ym[3]);
        *(float4*)(out_ym + mbase + 4) = make_float4(ym[4], ym[5], ym[6], ym[7]);
    }
}

extern "C" void kernel_launch(void* const* d_in, const int* in_sizes, int n_in,
                              void* d_out, int out_size) {
    const float* mask = (const float*)d_in[0];
    const float* xl   = (const float*)d_in[1];
    const float* yl   = (const float*)d_in[2];
    const float* cw   = (const float*)d_in[3];
    const float* cb   = (const float*)d_in[4];
    float* out = (float*)d_out;

    const int total = BB * HH * WV8;         // 1,048,576 threads (2 rows x 8 cols each)
    const int threads = 256;
    const int blocks = (total + threads - 1) / threads;
    fused_upsample_blend_conv_kernel<<<blocks, threads>>>(mask, xl, yl, cw, cb, out);
}